// round 12
// baseline (speedup 1.0000x reference)
#include <cuda_runtime.h>

#define ESP 1e-12f
#define C_DIM 8192
#define THREADS 256

__device__ double        g_accum;   // zero-init; reset by finalizer each run
__device__ unsigned int  g_ticket;  // zero-init; reset by finalizer each run

__device__ __forceinline__ float fsqrt_approx(float x) {
    float r;
    asm("sqrt.approx.f32 %0, %1;" : "=f"(r) : "f"(x));
    return r;
}

// R9 configuration with ONE change: default-policy non-coherent loads
// (__ldg) instead of evict-first streaming (__ldcs). Cache-policy A/B —
// the last untested knob. All else identical to the 149.6us best.
__global__ void __launch_bounds__(THREADS, 8) mfl_fused_kernel(
    const float* __restrict__ p,
    const float* __restrict__ g,
    float* __restrict__ out,
    int n_rows)
{
    const int row = blockIdx.x;
    const float4* __restrict__ p4 =
        reinterpret_cast<const float4*>(p + (size_t)row * C_DIM);
    const float4* __restrict__ g4 =
        reinterpret_cast<const float4*>(g + (size_t)row * C_DIM);
    const int tid = threadIdx.x;

    float sum = 0.0f;
    int   cnt = 0;

    // C_DIM/4 = 2048 float4s, 256 threads -> 8 iterations.
    #pragma unroll
    for (int i = 0; i < 8; i++) {
        float4 pv = __ldg(&p4[tid + i * THREADS]);
        float4 gv = __ldg(&g4[tid + i * THREADS]);

        #pragma unroll
        for (int k = 0; k < 4; k++) {
            float pe = (&pv.x)[k];
            float ge = (&gv.x)[k];
            float a = fmaf(pe, ge, ESP);
            float b = fmaf(1.0f - pe, 1.0f - ge, ESP);
            float l = 1.0f - (fsqrt_approx(a) + fsqrt_approx(b));
            bool nz = (ge != 0.0f);
            sum += nz ? l : 0.0f;
            cnt += nz ? 1 : 0;
        }
    }

    // Warp reduction
    #pragma unroll
    for (int o = 16; o > 0; o >>= 1) {
        sum += __shfl_down_sync(0xffffffffu, sum, o);
        cnt += __shfl_down_sync(0xffffffffu, cnt, o);
    }

    __shared__ float s_sum[THREADS / 32];
    __shared__ int   s_cnt[THREADS / 32];
    const int wid = tid >> 5;
    const int lid = tid & 31;
    if (lid == 0) {
        s_sum[wid] = sum;
        s_cnt[wid] = cnt;
    }
    __syncthreads();

    if (tid == 0) {
        float bsum = 0.0f;
        int   bcnt = 0;
        #pragma unroll
        for (int w = 0; w < THREADS / 32; w++) {
            bsum += s_sum[w];
            bcnt += s_cnt[w];
        }
        float row_loss = (bcnt > 0) ? (bsum / (float)bcnt) : 0.0f;

        atomicAdd(&g_accum, (double)row_loss);
        __threadfence();
        unsigned int t = atomicAdd(&g_ticket, 1u);
        if (t == (unsigned int)(gridDim.x - 1)) {
            // Last block: read-and-reset accumulator + ticket atomically so
            // every graph replay starts from zeroed state (matches the
            // zero-initialized first call), then emit the result.
            unsigned long long bits =
                atomicExch((unsigned long long*)&g_accum, 0ull);
            atomicExch(&g_ticket, 0u);
            double total = __longlong_as_double((long long)bits);
            out[0] = (float)(total / (double)n_rows);
        }
    }
}

extern "C" void kernel_launch(void* const* d_in, const int* in_sizes, int n_in,
                              void* d_out, int out_size) {
    const float* p = (const float*)d_in[0];
    const float* g = (const float*)d_in[1];
    float* out = (float*)d_out;

    const int total = in_sizes[0];
    const int n_rows = total / C_DIM;   // 16384

    mfl_fused_kernel<<<n_rows, THREADS>>>(p, g, out, n_rows);
}

// round 13
// speedup vs baseline: 1.0023x; 1.0023x over previous
#include <cuda_runtime.h>

#define ESP 1e-12f
#define C_DIM 8192
#define THREADS 256

__device__ double        g_accum;   // zero-init; reset by finalizer each run
__device__ unsigned int  g_ticket;  // zero-init; reset by finalizer each run

__device__ __forceinline__ float fsqrt_approx(float x) {
    float r;
    asm("sqrt.approx.f32 %0, %1;" : "=f"(r) : "f"(x));
    return r;
}

// FINAL KERNEL — session best 149.6us @ 7.07 TB/s (88-89% of HBM spec),
// rel_err 6.7e-8. Measured design rationale (12-round bracket):
//  - one 256-thread block per row, dynamic 16384-block grid: the HW CTA
//    distributor beats every static/persistent partition tried (R3 static
//    warp-chunks +11%, R5 ticket-persistent +3%, R10 128-thr blocks +3%)
//  - __launch_bounds__(256, 8) pins regs=32 -> 8 CTAs/SM. +3 regs was
//    measured to drop residency to 7/SM and cost ~6% DRAM util (R6).
//  - __ldcs float4 streaming loads; LDG.256 (R8) and default .nc (R12)
//    measured equivalent at the path-independent LTS/HBM ceiling.
//  - sqrt.approx.f32: single MUFU op, rel err ~3e-7, keeps the IEEE-sqrt
//    fixup sequence off the FMA pipe.
//  - double accumulation across rows (float per-row is safe: 8192-elem
//    sums; cross-row serial atomics need f64 to stay ~1e-8).
//  - fused last-block finalize with atomically self-resetting state:
//    graph-replay deterministic, zero auxiliary kernels.
__global__ void __launch_bounds__(THREADS, 8) mfl_fused_kernel(
    const float* __restrict__ p,
    const float* __restrict__ g,
    float* __restrict__ out,
    int n_rows)
{
    const int row = blockIdx.x;
    const float4* __restrict__ p4 =
        reinterpret_cast<const float4*>(p + (size_t)row * C_DIM);
    const float4* __restrict__ g4 =
        reinterpret_cast<const float4*>(g + (size_t)row * C_DIM);
    const int tid = threadIdx.x;

    float sum = 0.0f;
    int   cnt = 0;

    // C_DIM/4 = 2048 float4s, 256 threads -> 8 iterations. Streaming loads:
    // data is touched exactly once, keep it evict-first in L2.
    #pragma unroll
    for (int i = 0; i < 8; i++) {
        float4 pv = __ldcs(&p4[tid + i * THREADS]);
        float4 gv = __ldcs(&g4[tid + i * THREADS]);

        #pragma unroll
        for (int k = 0; k < 4; k++) {
            float pe = (&pv.x)[k];
            float ge = (&gv.x)[k];
            float a = fmaf(pe, ge, ESP);
            float b = fmaf(1.0f - pe, 1.0f - ge, ESP);
            float l = 1.0f - (fsqrt_approx(a) + fsqrt_approx(b));
            bool nz = (ge != 0.0f);
            sum += nz ? l : 0.0f;
            cnt += nz ? 1 : 0;
        }
    }

    // Warp reduction
    #pragma unroll
    for (int o = 16; o > 0; o >>= 1) {
        sum += __shfl_down_sync(0xffffffffu, sum, o);
        cnt += __shfl_down_sync(0xffffffffu, cnt, o);
    }

    __shared__ float s_sum[THREADS / 32];
    __shared__ int   s_cnt[THREADS / 32];
    const int wid = tid >> 5;
    const int lid = tid & 31;
    if (lid == 0) {
        s_sum[wid] = sum;
        s_cnt[wid] = cnt;
    }
    __syncthreads();

    if (tid == 0) {
        float bsum = 0.0f;
        int   bcnt = 0;
        #pragma unroll
        for (int w = 0; w < THREADS / 32; w++) {
            bsum += s_sum[w];
            bcnt += s_cnt[w];
        }
        float row_loss = (bcnt > 0) ? (bsum / (float)bcnt) : 0.0f;

        atomicAdd(&g_accum, (double)row_loss);
        __threadfence();
        unsigned int t = atomicAdd(&g_ticket, 1u);
        if (t == (unsigned int)(gridDim.x - 1)) {
            // Last block: read-and-reset accumulator + ticket atomically so
            // every graph replay starts from zeroed state (matches the
            // zero-initialized first call), then emit the result.
            unsigned long long bits =
                atomicExch((unsigned long long*)&g_accum, 0ull);
            atomicExch(&g_ticket, 0u);
            double total = __longlong_as_double((long long)bits);
            out[0] = (float)(total / (double)n_rows);
        }
    }
}

extern "C" void kernel_launch(void* const* d_in, const int* in_sizes, int n_in,
                              void* d_out, int out_size) {
    const float* p = (const float*)d_in[0];
    const float* g = (const float*)d_in[1];
    float* out = (float*)d_out;

    const int total = in_sizes[0];
    const int n_rows = total / C_DIM;   // 16384

    mfl_fused_kernel<<<n_rows, THREADS>>>(p, g, out, n_rows);
}